// round 2
// baseline (speedup 1.0000x reference)
#include <cuda_runtime.h>

#define B_  64
#define F_  256
#define T_  1024
#define H_  1024
#define O_  512

#define GRC 128           // recurrence CTAs (one wave, <=148 SMs)
#define NCOL 16           // Wh columns per CTA  (64 col-groups x 2 batch-halves)
#define NB   32           // batch rows per CTA
#define KCH  256          // k chunk staged in smem per step
#define WH_STRIDE 1026    // 1024 + 2 pad: per-col bank offset 2 -> conflict free 8B loads
#define S_STRIDE  260     // 256 + 4 pad: 16B aligned rows, bank offset 4

// -------- scratch (no allocations allowed; device globals) --------
__device__ float g_xT[(size_t)T_ * B_ * F_];        //  67 MB
__device__ float g_pre[(size_t)T_ * B_ * H_];       // 268 MB  (T,B,H)
__device__ float g_states[(size_t)B_ * T_ * H_];    // 268 MB  (B,T,H)
__device__ float g_s[2][B_ * H_];
__device__ unsigned g_bar;

typedef unsigned long long ull;
union F2U { ull u; float2 f; };

__device__ __forceinline__ void fma2(ull& d, ull a, ull b) {
    asm("fma.rn.f32x2 %0, %1, %2, %0;" : "+l"(d) : "l"(a), "l"(b));
}

// ---------------- init: zero state buffer 0 + barrier ----------------
__global__ void k_init() {
    int idx = blockIdx.x * blockDim.x + threadIdx.x;
    for (int i = idx; i < B_ * H_; i += gridDim.x * blockDim.x) g_s[0][i] = 0.0f;
    if (idx == 0) g_bar = 0u;
}

// ---------------- transpose x(B,F,T) -> xT(T*B, F) ----------------
__global__ void k_transpose(const float* __restrict__ x) {
    __shared__ float tile[32][33];
    int b  = blockIdx.z;
    int f0 = blockIdx.y * 32;
    int t0 = blockIdx.x * 32;
    int tx = threadIdx.x, ty = threadIdx.y;     // 32 x 8
#pragma unroll
    for (int i = 0; i < 4; i++) {
        int f = f0 + ty + i * 8;
        tile[ty + i * 8][tx] = x[((size_t)b * F_ + f) * T_ + t0 + tx];
    }
    __syncthreads();
#pragma unroll
    for (int i = 0; i < 4; i++) {
        int t = t0 + ty + i * 8;
        g_xT[((size_t)t * B_ + b) * F_ + f0 + tx] = tile[tx][ty + i * 8];
    }
}

// ---------------- fp32 SGEMM with f32x2 packed FMA ----------------
// C[M,N] = A[M,K] @ B[K,N] + bias[N].  Tiles: 128x64x16, 256 thr, 8x4/thread.
// Accumulators are f32x2 lanes over (even k, odd k); horizontal add at the end.
__global__ void __launch_bounds__(256) k_sgemm(const float* __restrict__ A,
                                               const float* __restrict__ Bm,
                                               const float* __restrict__ bias,
                                               float* __restrict__ C,
                                               int M, int N, int K) {
    __shared__ __align__(16) float As[128 * 18];
    __shared__ __align__(16) float Bs[64 * 18];
    int tid = threadIdx.x;
    int tx = tid & 15, ty = tid >> 4;
    int n0 = blockIdx.x * 64;
    int m0 = blockIdx.y * 128;

    ull acc[8][4];
#pragma unroll
    for (int i = 0; i < 8; i++)
#pragma unroll
        for (int j = 0; j < 4; j++) acc[i][j] = 0ull;

    for (int k0 = 0; k0 < K; k0 += 16) {
        // A tile: 128 rows x 16 k -> As[row][k] (stride 18)
#pragma unroll
        for (int l = 0; l < 2; l++) {
            int j = tid + l * 256;               // 0..511 float4s
            int row = j >> 2, kq = (j & 3) * 4;
            float4 v = *reinterpret_cast<const float4*>(&A[(size_t)(m0 + row) * K + k0 + kq]);
            As[row * 18 + kq + 0] = v.x;
            As[row * 18 + kq + 1] = v.y;
            As[row * 18 + kq + 2] = v.z;
            As[row * 18 + kq + 3] = v.w;
        }
        // B tile: 16 k x 64 n -> Bs[n][k] (transposed, stride 18)
        {
            int k = tid >> 4, nq = (tid & 15) * 4;
            float4 v = *reinterpret_cast<const float4*>(&Bm[(size_t)(k0 + k) * N + n0 + nq]);
            Bs[(nq + 0) * 18 + k] = v.x;
            Bs[(nq + 1) * 18 + k] = v.y;
            Bs[(nq + 2) * 18 + k] = v.z;
            Bs[(nq + 3) * 18 + k] = v.w;
        }
        __syncthreads();
#pragma unroll
        for (int p = 0; p < 8; p++) {            // 8 k-pairs
            ull a2[8], b2[4];
#pragma unroll
            for (int i = 0; i < 8; i++)
                a2[i] = *reinterpret_cast<const ull*>(&As[(ty * 8 + i) * 18 + p * 2]);
#pragma unroll
            for (int j = 0; j < 4; j++)
                b2[j] = *reinterpret_cast<const ull*>(&Bs[(tx * 4 + j) * 18 + p * 2]);
#pragma unroll
            for (int i = 0; i < 8; i++)
#pragma unroll
                for (int j = 0; j < 4; j++) fma2(acc[i][j], a2[i], b2[j]);
        }
        __syncthreads();
    }
#pragma unroll
    for (int i = 0; i < 8; i++) {
#pragma unroll
        for (int j = 0; j < 4; j++) {
            F2U u; u.u = acc[i][j];
            int n = n0 + tx * 4 + j;
            C[(size_t)(m0 + ty * 8 + i) * N + n] = u.f.x + u.f.y + bias[n];
        }
    }
}

// ---------------- persistent recurrence ----------------
// 128 CTAs: CTA = (col-group cg 0..63, batch-half bh 0..1).
// Owns Wh[:, cg*16 .. cg*16+15] in SMEM for the whole kernel.
// Per step: s_new[b, h] = tanh(pre[t,b,h] + sum_k s[b,k]*Wh[k,h]) for its
// 32 batch rows x 16 cols. Grid barrier between steps; state double-buffered.
__global__ void __launch_bounds__(256, 1) k_rnn(const float* __restrict__ Wh) {
    extern __shared__ __align__(16) float smem[];
    float* wh  = smem;                       // [NCOL][WH_STRIDE]
    float* ssm = smem + NCOL * WH_STRIDE;    // [NB][S_STRIDE]

    int tid = threadIdx.x;
    int cta = blockIdx.x;
    int bh  = cta & 1;
    int cg  = cta >> 1;
    int h0  = cg * NCOL;
    int bOff = bh * NB;

    // load Wh slice, transposed to [col][k]
    for (int idx = tid; idx < NCOL * 1024; idx += 256) {
        int k = idx >> 4, c = idx & 15;
        wh[c * WH_STRIDE + k] = Wh[(size_t)k * H_ + h0 + c];
    }

    int col  = tid & 15;          // 0..15
    int brel = tid >> 4;          // 0..15
    const float* whp = wh + col * WH_STRIDE;

    for (int t = 0; t < T_; t++) {
        const float* cur = g_s[t & 1];
        float* nxt = g_s[(t + 1) & 1];
        ull aa0 = 0, aa1 = 0, ba0 = 0, ba1 = 0;

        for (int k0 = 0; k0 < H_; k0 += KCH) {
            __syncthreads();                  // ssm safe to overwrite
            // stage s[bOff..bOff+31][k0..k0+255] (L1 bypass: buffer is reused)
#pragma unroll
            for (int l = 0; l < 8; l++) {
                int j = tid + l * 256;        // 0..2047 float4s
                int b = j >> 6, q = (j & 63) * 4;
                float4 v = __ldcg(reinterpret_cast<const float4*>(
                    &cur[(size_t)(bOff + b) * H_ + k0 + q]));
                *reinterpret_cast<float4*>(&ssm[b * S_STRIDE + q]) = v;
            }
            __syncthreads();

            const float* wk = whp + k0;
            const float* sa = ssm + brel * S_STRIDE;
            const float* sb = ssm + (brel + 16) * S_STRIDE;
#pragma unroll 8
            for (int q = 0; q < KCH; q += 4) {
                ull w0 = *reinterpret_cast<const ull*>(&wk[q]);
                ull w1 = *reinterpret_cast<const ull*>(&wk[q + 2]);
                ulonglong2 va = *reinterpret_cast<const ulonglong2*>(&sa[q]);
                ulonglong2 vb = *reinterpret_cast<const ulonglong2*>(&sb[q]);
                fma2(aa0, va.x, w0); fma2(aa1, va.y, w1);
                fma2(ba0, vb.x, w0); fma2(ba1, vb.y, w1);
            }
        }

        F2U u0, u1, u2, u3;
        u0.u = aa0; u1.u = aa1; u2.u = ba0; u3.u = ba1;
        float da = (u0.f.x + u0.f.y) + (u1.f.x + u1.f.y);
        float db = (u2.f.x + u2.f.y) + (u3.f.x + u3.f.y);

        int h  = h0 + col;
        int b0 = bOff + brel;
        int b1 = b0 + 16;
        float v0 = tanhf(g_pre[((size_t)t * B_ + b0) * H_ + h] + da);
        float v1 = tanhf(g_pre[((size_t)t * B_ + b1) * H_ + h] + db);
        g_states[((size_t)b0 * T_ + t) * H_ + h] = v0;
        g_states[((size_t)b1 * T_ + t) * H_ + h] = v1;
        nxt[b0 * H_ + h] = v0;
        nxt[b1 * H_ + h] = v1;

        // grid barrier
        __syncthreads();
        if (tid == 0) {
            __threadfence();
            atomicAdd(&g_bar, 1u);
            unsigned target = (unsigned)(t + 1) * GRC;
            while (*((volatile unsigned*)&g_bar) < target) { }
        }
        __syncthreads();
    }
}

// ---------------- launch ----------------
extern "C" void kernel_launch(void* const* d_in, const int* in_sizes, int n_in,
                              void* d_out, int out_size) {
    const float* x    = (const float*)d_in[0];
    const float* Wx   = (const float*)d_in[1];
    const float* Wh   = (const float*)d_in[2];
    const float* bias = (const float*)d_in[3];
    const float* Wout = (const float*)d_in[4];
    const float* bout = (const float*)d_in[5];
    float* out = (float*)d_out;

    float *pXT, *pPre, *pStates;
    cudaGetSymbolAddress((void**)&pXT, g_xT);
    cudaGetSymbolAddress((void**)&pPre, g_pre);
    cudaGetSymbolAddress((void**)&pStates, g_states);

    int rnn_smem = (NCOL * WH_STRIDE + NB * S_STRIDE) * (int)sizeof(float);
    cudaFuncSetAttribute(k_rnn, cudaFuncAttributeMaxDynamicSharedMemorySize, rnn_smem);

    k_init<<<64, 256>>>();
    k_transpose<<<dim3(T_ / 32, F_ / 32, B_), dim3(32, 8)>>>(x);
    // pre = xT @ Wx + b     (M=65536, N=1024, K=256)
    k_sgemm<<<dim3(H_ / 64, (T_ * B_) / 128), 256>>>(pXT, Wx, bias, pPre,
                                                     T_ * B_, H_, F_);
    // recurrence -> g_states
    k_rnn<<<GRC, 256, rnn_smem>>>(Wh);
    // out = states @ Wout + bout   (M=65536, N=512, K=1024)
    k_sgemm<<<dim3(O_ / 64, (B_ * T_) / 128), 256>>>(pStates, Wout, bout, out,
                                                     B_ * T_, O_, H_);
}

// round 4
// speedup vs baseline: 1.4940x; 1.4940x over previous
#include <cuda_runtime.h>

#define B_  64
#define F_  256
#define T_  1024
#define H_  1024
#define O_  512

#define GRC   128         // recurrence CTAs (one wave)
#define CPC   32          // cols per CTA (32 col-groups)
#define RPC   16          // batch rows per CTA (4 batch-quarters)
#define KSPL  8           // k-split (warp = one k-slice of 128)
#define KPT   128         // k per thread
#define WST   1028        // smem stride (floats): bank offset 4, 16B aligned

// -------- scratch (no allocations allowed; device globals) --------
__device__ float g_xT[(size_t)T_ * B_ * F_];
__device__ float g_pre[(size_t)T_ * B_ * H_];       // (T,B,H)
__device__ float g_states[(size_t)B_ * T_ * H_];    // (B,T,H)
__device__ float g_s[2][B_ * H_];
__device__ unsigned g_bar;

typedef unsigned long long ull;
union F2U { ull u; float2 f; };

__device__ __forceinline__ void fma2(ull& d, ull a, ull b) {
    asm("fma.rn.f32x2 %0, %1, %2, %0;" : "+l"(d) : "l"(a), "l"(b));
}

// ---------------- init: zero state buffer 0 + barrier ----------------
__global__ void k_init() {
    int idx = blockIdx.x * blockDim.x + threadIdx.x;
    for (int i = idx; i < B_ * H_; i += gridDim.x * blockDim.x) g_s[0][i] = 0.0f;
    if (idx == 0) g_bar = 0u;
}

// ---------------- transpose x(B,F,T) -> xT(T*B, F) ----------------
__global__ void k_transpose(const float* __restrict__ x) {
    __shared__ float tile[32][33];
    int b  = blockIdx.z;
    int f0 = blockIdx.y * 32;
    int t0 = blockIdx.x * 32;
    int tx = threadIdx.x, ty = threadIdx.y;     // 32 x 8
#pragma unroll
    for (int i = 0; i < 4; i++) {
        int f = f0 + ty + i * 8;
        tile[ty + i * 8][tx] = x[((size_t)b * F_ + f) * T_ + t0 + tx];
    }
    __syncthreads();
#pragma unroll
    for (int i = 0; i < 4; i++) {
        int t = t0 + ty + i * 8;
        g_xT[((size_t)t * B_ + b) * F_ + f0 + tx] = tile[tx][ty + i * 8];
    }
}

// ---------------- fp32 SGEMM with f32x2 packed FMA ----------------
__global__ void __launch_bounds__(256) k_sgemm(const float* __restrict__ A,
                                               const float* __restrict__ Bm,
                                               const float* __restrict__ bias,
                                               float* __restrict__ C,
                                               int M, int N, int K) {
    __shared__ __align__(16) float As[128 * 18];
    __shared__ __align__(16) float Bs[64 * 18];
    int tid = threadIdx.x;
    int tx = tid & 15, ty = tid >> 4;
    int n0 = blockIdx.x * 64;
    int m0 = blockIdx.y * 128;

    ull acc[8][4];
#pragma unroll
    for (int i = 0; i < 8; i++)
#pragma unroll
        for (int j = 0; j < 4; j++) acc[i][j] = 0ull;

    for (int k0 = 0; k0 < K; k0 += 16) {
#pragma unroll
        for (int l = 0; l < 2; l++) {
            int j = tid + l * 256;
            int row = j >> 2, kq = (j & 3) * 4;
            float4 v = *reinterpret_cast<const float4*>(&A[(size_t)(m0 + row) * K + k0 + kq]);
            As[row * 18 + kq + 0] = v.x;
            As[row * 18 + kq + 1] = v.y;
            As[row * 18 + kq + 2] = v.z;
            As[row * 18 + kq + 3] = v.w;
        }
        {
            int k = tid >> 4, nq = (tid & 15) * 4;
            float4 v = *reinterpret_cast<const float4*>(&Bm[(size_t)(k0 + k) * N + n0 + nq]);
            Bs[(nq + 0) * 18 + k] = v.x;
            Bs[(nq + 1) * 18 + k] = v.y;
            Bs[(nq + 2) * 18 + k] = v.z;
            Bs[(nq + 3) * 18 + k] = v.w;
        }
        __syncthreads();
#pragma unroll
        for (int p = 0; p < 8; p++) {
            ull a2[8], b2[4];
#pragma unroll
            for (int i = 0; i < 8; i++)
                a2[i] = *reinterpret_cast<const ull*>(&As[(ty * 8 + i) * 18 + p * 2]);
#pragma unroll
            for (int j = 0; j < 4; j++)
                b2[j] = *reinterpret_cast<const ull*>(&Bs[(tx * 4 + j) * 18 + p * 2]);
#pragma unroll
            for (int i = 0; i < 8; i++)
#pragma unroll
                for (int j = 0; j < 4; j++) fma2(acc[i][j], a2[i], b2[j]);
        }
        __syncthreads();
    }
#pragma unroll
    for (int i = 0; i < 8; i++) {
#pragma unroll
        for (int j = 0; j < 4; j++) {
            F2U u; u.u = acc[i][j];
            int n = n0 + tx * 4 + j;
            C[(size_t)(m0 + ty * 8 + i) * N + n] = u.f.x + u.f.y + bias[n];
        }
    }
}

// ---------------- persistent recurrence (register-tiled, split-K) --------
// 128 CTAs = 32 col-groups x 4 batch-quarters. CTA keeps Wh[:, h0..h0+31]
// in SMEM for all steps. Thread tile: 4 cols x 4 rows, k-split 8 (warp =
// one 128-k slice; stages its own s slice with only __syncwarp).
// SMEM: wh[32][WST] + ssm[16][WST]; ssm region reused as reduce buffer.
__global__ void __launch_bounds__(256, 1) k_rnn(const float* __restrict__ Wh) {
    extern __shared__ __align__(16) float smem[];
    float* wh  = smem;                 // [CPC][WST]
    float* ssm = smem + CPC * WST;     // [RPC][WST]; also reduce buffer

    int tid  = threadIdx.x;
    int lane = tid & 31;
    int ks   = tid >> 5;               // warp id = k-slice 0..7
    int cgrp = tid & 7;                // col sub-index
    int bg   = (tid >> 3) & 3;         // row sub-index
    int cta  = blockIdx.x;
    int cg   = cta >> 2;               // 0..31
    int bq   = cta & 3;                // 0..3
    int h0   = cg * CPC;
    int b0   = bq * RPC;
    int k0s  = ks * KPT;

    // load Wh slice, transposed to [col][k]
    for (int idx = tid; idx < CPC * H_; idx += 256) {
        int k = idx >> 5, c = idx & 31;
        wh[c * WST + k] = Wh[(size_t)k * H_ + h0 + c];
    }
    __syncthreads();

    // thread cols: cgrp + 8i ; thread rows: bg + 4j  (bank-conflict-free)
    const float* wp[4];
    const float* sp[4];
#pragma unroll
    for (int i = 0; i < 4; i++) wp[i] = wh + (cgrp + 8 * i) * WST + k0s;
#pragma unroll
    for (int j = 0; j < 4; j++) sp[j] = ssm + (bg + 4 * j) * WST + k0s;

    // finalize ownership: 2 outputs per thread
    int o0 = tid * 2;

    for (int t = 0; t < T_; t++) {
        const float* cur = g_s[t & 1];
        float* nxt = g_s[(t + 1) & 1];

        // stage this warp's own k-slice: 16 rows x 128 k (L2, bypass L1)
#pragma unroll 4
        for (int r = 0; r < RPC; r++) {
            float4 v = __ldcg(reinterpret_cast<const float4*>(
                &cur[(size_t)(b0 + r) * H_ + k0s + lane * 4]));
            *reinterpret_cast<float4*>(&ssm[r * WST + k0s + lane * 4]) = v;
        }
        __syncwarp();

        // prefetch pre values for the two outputs this thread finalizes
        int ca0 = o0 >> 4, ra0 = o0 & 15;
        int ca1 = (o0 + 1) >> 4, ra1 = (o0 + 1) & 15;
        float p0 = __ldcs(&g_pre[((size_t)t * B_ + b0 + ra0) * H_ + h0 + ca0]);
        float p1 = __ldcs(&g_pre[((size_t)t * B_ + b0 + ra1) * H_ + h0 + ca1]);

        ull acc[4][4];
#pragma unroll
        for (int i = 0; i < 4; i++)
#pragma unroll
            for (int j = 0; j < 4; j++) acc[i][j] = 0ull;

#pragma unroll 2
        for (int kk = 0; kk < KPT; kk += 4) {
            ulonglong2 w[4], s[4];
#pragma unroll
            for (int i = 0; i < 4; i++)
                w[i] = *reinterpret_cast<const ulonglong2*>(wp[i] + kk);
#pragma unroll
            for (int j = 0; j < 4; j++)
                s[j] = *reinterpret_cast<const ulonglong2*>(sp[j] + kk);
#pragma unroll
            for (int i = 0; i < 4; i++)
#pragma unroll
                for (int j = 0; j < 4; j++) {
                    fma2(acc[i][j], w[i].x, s[j].x);
                    fma2(acc[i][j], w[i].y, s[j].y);
                }
        }

        // split-K reduce through ssm region: partial[out][ks], stride 9
        __syncthreads();                       // all warps done reading ssm
        float* red = ssm;
#pragma unroll
        for (int i = 0; i < 4; i++)
#pragma unroll
            for (int j = 0; j < 4; j++) {
                F2U u; u.u = acc[i][j];
                int out = (cgrp + 8 * i) * 16 + (bg + 4 * j);
                red[out * 9 + ks] = u.f.x + u.f.y;
            }
        __syncthreads();

        // finalize 2 outputs: sum partials, +pre, tanh, store
        float s0 = 0.f, s1 = 0.f;
#pragma unroll
        for (int q = 0; q < KSPL; q++) {
            s0 += red[o0 * 9 + q];
            s1 += red[(o0 + 1) * 9 + q];
        }
        float v0 = tanhf(p0 + s0);
        float v1 = tanhf(p1 + s1);
        int hb0 = h0 + ca0, bb0 = b0 + ra0;
        int hb1 = h0 + ca1, bb1 = b0 + ra1;
        g_states[((size_t)bb0 * T_ + t) * H_ + hb0] = v0;
        g_states[((size_t)bb1 * T_ + t) * H_ + hb1] = v1;
        nxt[bb0 * H_ + hb0] = v0;
        nxt[bb1 * H_ + hb1] = v1;

        // grid barrier
        __syncthreads();
        if (tid == 0) {
            __threadfence();
            atomicAdd(&g_bar, 1u);
            unsigned target = (unsigned)(t + 1) * GRC;
            while (*((volatile unsigned*)&g_bar) < target) { }
        }
        __syncthreads();
    }
}

// ---------------- launch ----------------
extern "C" void kernel_launch(void* const* d_in, const int* in_sizes, int n_in,
                              void* d_out, int out_size) {
    const float* x    = (const float*)d_in[0];
    const float* Wx   = (const float*)d_in[1];
    const float* Wh   = (const float*)d_in[2];
    const float* bias = (const float*)d_in[3];
    const float* Wout = (const float*)d_in[4];
    const float* bout = (const float*)d_in[5];
    float* out = (float*)d_out;

    float *pXT, *pPre, *pStates;
    cudaGetSymbolAddress((void**)&pXT, g_xT);
    cudaGetSymbolAddress((void**)&pPre, g_pre);
    cudaGetSymbolAddress((void**)&pStates, g_states);

    int rnn_smem = (CPC + RPC) * WST * (int)sizeof(float);   // 197376 B
    cudaFuncSetAttribute(k_rnn, cudaFuncAttributeMaxDynamicSharedMemorySize, rnn_smem);

    k_init<<<64, 256>>>();
    k_transpose<<<dim3(T_ / 32, F_ / 32, B_), dim3(32, 8)>>>(x);
    // pre = xT @ Wx + b     (M=65536, N=1024, K=256)
    k_sgemm<<<dim3(H_ / 64, (T_ * B_) / 128), 256>>>(pXT, Wx, bias, pPre,
                                                     T_ * B_, H_, F_);
    // recurrence -> g_states
    k_rnn<<<GRC, 256, rnn_smem>>>(Wh);
    // out = states @ Wout + bout   (M=65536, N=512, K=1024)
    k_sgemm<<<dim3(O_ / 64, (B_ * T_) / 128), 256>>>(pStates, Wout, bout, out,
                                                     B_ * T_, O_, H_);
}